// round 16
// baseline (speedup 1.0000x reference)
#include <cuda_runtime.h>
#include <cstdint>
#include <math.h>

#define HH 24
#define WW 24
#define NPIX 576
#define DD 1024
#define BB 32
#define KS 256
#define MT 128
#define NT 577

// ---------------- scratch (device globals; no allocation allowed) ----------
__device__ float g_affp[8][BB * NPIX * 9];   // partial 9-logits per d-eighth
__device__ float g_dotp[8][BB * NPIX];       // partial x.u per d-eighth
__device__ int   g_mem[BB * NPIX];           // member lists (grouped by slot)
__device__ float g_qpartT[8][BB * DD];       // partial Q_cls, layout [d*32+b]
__device__ float g_upart[64][BB * DD];       // partial u (per d-chunk)
__device__ float g_u[BB * DD];               // u = Q_cls @ v_w
__device__ int   g_selstart[BB * MT];        // member offsets of selected slots
__device__ int   g_selcnt[BB * MT];          // counts of selected slots

// ---------------- Kernel 1: Q_cls partials (transposed, shuffle-free) ------
__global__ void k_qcls(const float* __restrict__ tok2d,
                       const float* __restrict__ qw) {
    __shared__ float s_cls[128 * 33];   // [e][b], pad 33 -> conflict-free
    __shared__ float s_qw[8 * 128];     // [warp-d][e]
    const int t = threadIdx.x, lane = t & 31, w = t >> 5;
    const int ec = blockIdx.y;
    const int d = blockIdx.x * 8 + w;
    for (int l = t; l < 32 * 128; l += 256) {
        int b = l >> 7, e = l & 127;
        s_cls[e * 33 + b] = tok2d[(size_t)b * NT * DD + ec * 128 + e];
    }
    for (int l = t; l < 8 * 128; l += 256) {
        int wd = l >> 7, e = l & 127;
        s_qw[l] = qw[(size_t)(blockIdx.x * 8 + wd) * DD + ec * 128 + e];
    }
    __syncthreads();
    float acc = 0.f;
    const float* qrow = &s_qw[w * 128];
#pragma unroll 8
    for (int e = 0; e < 128; e++)
        acc += qrow[e] * s_cls[e * 33 + lane];
    g_qpartT[ec][d * 32 + lane] = acc;
}

// ---------------- Kernel 2: u partials, 64 d-chunks x 2 b-halves -----------
__global__ void k_u(const float* __restrict__ vw,
                    const float* __restrict__ qb) {
    __shared__ float s_qc[16 * 16];
    const int t = threadIdx.x;
    const int e = blockIdx.x * 128 + t;
    const int dc0 = blockIdx.y * 16;
    const int b0 = blockIdx.z * 16;
    for (int l = t; l < 16 * 16; l += 128) {
        int d = l >> 4, b = l & 15;
        float v = qb[dc0 + d];
#pragma unroll
        for (int z = 0; z < 8; z++) v += g_qpartT[z][(dc0 + d) * 32 + b0 + b];
        s_qc[l] = v;
    }
    __syncthreads();
    float acc[16];
#pragma unroll
    for (int b = 0; b < 16; b++) acc[b] = 0.f;
#pragma unroll
    for (int dd = 0; dd < 16; dd++) {
        float v = vw[(size_t)(dc0 + dd) * DD + e];
        const float4* q4 = (const float4*)&s_qc[dd * 16];
#pragma unroll
        for (int jj = 0; jj < 4; jj++) {
            float4 q = q4[jj];
            acc[4 * jj + 0] += q.x * v;
            acc[4 * jj + 1] += q.y * v;
            acc[4 * jj + 2] += q.z * v;
            acc[4 * jj + 3] += q.w * v;
        }
    }
#pragma unroll
    for (int b = 0; b < 16; b++)
        g_upart[blockIdx.y][(b0 + b) * DD + e] = acc[b];
}

// ---------------- Kernel 2b: sum u partials (float4) -----------------------
__global__ void k_sumu() {
    int idx = blockIdx.x * 256 + threadIdx.x;   // float4 index
    float4 s = {0.f, 0.f, 0.f, 0.f};
#pragma unroll
    for (int z = 0; z < 64; z++) {
        float4 v = ((const float4*)g_upart[z])[idx];
        s.x += v.x; s.y += v.y; s.z += v.z; s.w += v.w;
    }
    ((float4*)g_u)[idx] = s;
}

// ---------------- Kernel 3: FUSED dwconv + pointwise + x.u dot -------------
// grid (6 hgroups of 4 rows, B, 8 d-eighths), 384 threads.
// 8 phases of 16-d-lane tiles, cp.async double buffered, stride-172 taps.
#define TL_ROW 28
#define TL_LANE 172
__global__ void __launch_bounds__(384) k_affdw(const float* __restrict__ tok2d,
                        const float* __restrict__ dww,
                        const float* __restrict__ pww) {
    __shared__ float s_tile[2][16 * TL_LANE];  // 22016 B
    __shared__ float s_dw12[128 * 12];         // 6144 B
    __shared__ float s_u[128];                 // 512 B
    const int t  = threadIdx.x;
    const int h0 = blockIdx.x * 4;
    const int b  = blockIdx.y;
    const int z  = blockIdx.z;

    for (int l = t; l < 128 * 9; l += 384) {
        int dq = l / 9, k = l - dq * 9;
        s_dw12[dq * 12 + k] = dww[z * 128 * 9 + l];
    }
    if (t < 128) s_u[t] = g_u[b * DD + z * 128 + t];

    const int dl = t & 15;            // d-lane
    const int p0 = t >> 4;            // 0..23
    const int qr = p0 / 6;            // pixel row within group
    const int qw = (p0 % 6) * 4;      // base pixel col

    const unsigned int s_tile_a =
        (unsigned int)__cvta_generic_to_shared(&s_tile[0][0]);
    const char* gsrc0 = (const char*)(tok2d + (size_t)(b * NT + 1) * DD + z * 128 + dl);
    const unsigned int lane_off = (unsigned int)((dl * TL_LANE) << 2);
    const float* pwbase = pww + z * 128 + dl;   // + o*DD + ch*16

    unsigned int spos[7];
    unsigned int goff[7];
    int          gsz[7];
    int niter = 0;
    {
        int r = 0, c = p0;
#pragma unroll
        for (int i = 0; i < 7; i++) {
            int l = t + i * 384;
            if (l < 2496) {
                int gh = h0 + r - 1;
                int gw = c - 1;
                bool ok = ((unsigned)gh < HH) && ((unsigned)gw < WW);
                spos[i] = (unsigned int)((r * TL_ROW + c) << 2);
                goff[i] = ok ? (unsigned int)(((gh * WW + gw) * DD) * 4) : 0u;
                gsz[i]  = ok ? 4 : 0;
                niter = i + 1;
                c += 24;
                if (c >= 26) { c -= 26; r += 1; }
            }
        }
    }

#define ISSUE(CH, BUF)                                                          \
    {                                                                           \
        const char* gsrc = gsrc0 + (CH) * 64;  /* 16 floats */                  \
        unsigned int sb = s_tile_a + ((BUF) ? (unsigned int)((16 * TL_LANE) << 2) : 0u) + lane_off; \
        _Pragma("unroll")                                                       \
        for (int i = 0; i < 7; i++) {                                           \
            if (i < niter) {                                                    \
                asm volatile("cp.async.ca.shared.global [%0], [%1], 4, %2;"     \
                             :: "r"(sb + spos[i]), "l"(gsrc + goff[i]), "r"(gsz[i])); \
            }                                                                   \
        }                                                                       \
        asm volatile("cp.async.commit_group;" ::: "memory");                    \
    }

    float acc[40];
#pragma unroll
    for (int i = 0; i < 40; i++) acc[i] = 0.f;

    ISSUE(0, 0)
    asm volatile("cp.async.wait_group 0;" ::: "memory");
    __syncthreads();

    for (int ch = 0; ch < 8; ch++) {
        if (ch < 7) ISSUE(ch + 1, (ch + 1) & 1)
        const int dq = ch * 16 + dl;
        float wd[9], wp[9];
        {
            const float4* w4 = (const float4*)&s_dw12[dq * 12];
            float4 a = w4[0], bb4 = w4[1], c4 = w4[2];
            wd[0]=a.x; wd[1]=a.y; wd[2]=a.z; wd[3]=a.w;
            wd[4]=bb4.x; wd[5]=bb4.y; wd[6]=bb4.z; wd[7]=bb4.w;
            wd[8]=c4.x;
            const float* pwp = pwbase + ch * 16;
#pragma unroll
            for (int o = 0; o < 9; o++) wp[o] = pwp[o * DD];
        }
        const float uv = s_u[dq];
        const float* tp = &s_tile[ch & 1][dl * TL_LANE];
        float tv[3][6];
#pragma unroll
        for (int kh = 0; kh < 3; kh++) {
            const float* rp = tp + (qr + kh) * TL_ROW + qw;
            float4 v4 = *(const float4*)rp;
            float2 v2 = *(const float2*)(rp + 4);
            tv[kh][0] = v4.x; tv[kh][1] = v4.y; tv[kh][2] = v4.z;
            tv[kh][3] = v4.w; tv[kh][4] = v2.x; tv[kh][5] = v2.y;
        }
#pragma unroll
        for (int px = 0; px < 4; px++) {
            float dwv = 0.f;
#pragma unroll
            for (int kh = 0; kh < 3; kh++)
#pragma unroll
                for (int kw = 0; kw < 3; kw++)
                    dwv += tv[kh][px + kw] * wd[kh * 3 + kw];
#pragma unroll
            for (int o = 0; o < 9; o++) acc[px * 9 + o] += dwv * wp[o];
            acc[36 + px] += tv[1][px + 1] * uv;
        }
        if (ch < 7) {
            asm volatile("cp.async.wait_group 0;" ::: "memory");
            __syncthreads();
        }
    }
#undef ISSUE

#pragma unroll
    for (int i = 0; i < 40; i++)
#pragma unroll
        for (int off = 8; off; off >>= 1)
            acc[i] += __shfl_xor_sync(0xffffffffu, acc[i], off);

    if (dl == 0) {
#pragma unroll
        for (int px = 0; px < 4; px++) {
            int n = (h0 + qr) * WW + qw + px;
            float* dst = &g_affp[z][(b * NPIX + n) * 9];
#pragma unroll
            for (int o = 0; o < 9; o++) dst[o] = acc[px * 9 + o];
            g_dotp[z][b * NPIX + n] = acc[36 + px];
        }
    }
}

// ---------------- Kernel 4: parents + clusters + scores + top-128 ----------
__global__ void k_cluster(const float* __restrict__ pwb) {
    __shared__ int s_par[NPIX], s_cnt[NPIX], s_hist[NPIX + 1];
    __shared__ int s_flag[NPIX], s_slotof[NPIX];
    __shared__ int s_startsh[KS], s_cntsh[KS];
    __shared__ int s_mem[NPIX];
    __shared__ float s_p[NPIX];
    __shared__ float ss[KS];
    __shared__ int sfl[KS];
    __shared__ int s_cstar, s_take;
    const int i = threadIdx.x;
    const int b = blockIdx.x;

    {
        float pv = 0.f;
#pragma unroll
        for (int z = 0; z < 8; z++) pv += g_dotp[z][b * NPIX + i];
        s_p[i] = pv;
    }
    {
        float l9[9];
#pragma unroll
        for (int o = 0; o < 9; o++) l9[o] = pwb[o];
#pragma unroll
        for (int z = 0; z < 8; z++) {
            const float* src = &g_affp[z][(b * NPIX + i) * 9];
#pragma unroll
            for (int o = 0; o < 9; o++) l9[o] += src[o];
        }
        float mx = -1e30f;
#pragma unroll
        for (int o = 0; o < 9; o++) mx = fmaxf(mx, l9[o]);
        float e[9];
#pragma unroll
        for (int o = 0; o < 9; o++) e[o] = expf(l9[o] - mx);
        const int h = i / WW, w = i - (i / WW) * WW;
        float cs[9]; int cid[9]; int m = 0;
        for (int k = 0; k < 9; k++) {
            int dy = k / 3 - 1, dx = k % 3 - 1;
            int ny = min(max(h + dy, 0), HH - 1);
            int nx = min(max(w + dx, 0), WW - 1);
            int col = ny * WW + nx;
            int found = -1;
            for (int jj = 0; jj < m; jj++) if (cid[jj] == col) { found = jj; break; }
            if (found >= 0) cs[found] += e[k];
            else { cid[m] = col; cs[m] = e[k]; m++; }
        }
        int best = cid[0]; float bs = cs[0];
        for (int jj = 1; jj < m; jj++)
            if (cs[jj] > bs || (cs[jj] == bs && cid[jj] < best)) { bs = cs[jj]; best = cid[jj]; }
        s_par[i] = best;
    }
    __syncthreads();
    for (int it = 0; it < 6; it++) {
        int v = s_par[s_par[i]];
        __syncthreads();
        s_par[i] = v;
        __syncthreads();
    }
    s_cnt[i] = 0; s_hist[i] = 0;
    if (i == 0) s_hist[NPIX] = 0;
    __syncthreads();
    atomicAdd(&s_cnt[s_par[i]], 1);
    __syncthreads();
    atomicAdd(&s_hist[s_cnt[i]], 1);
    __syncthreads();
    {
        int nrep = (i == 0) ? 2 : 1;
        for (int rep = 0; rep < nrep; rep++) {
            int v = (rep == 0) ? i : NPIX;
            int gt = 0;
            for (int vv = v + 1; vv <= NPIX; vv++) gt += s_hist[vv];
            if (gt < KS && gt + s_hist[v] >= KS) { s_cstar = v; s_take = KS - gt; }
        }
    }
    __syncthreads();
    const int cstar = s_cstar, take = s_take;
    const int ci = s_cnt[i];
    int eqb = 0;
    for (int j = 0; j < i; j++) eqb += (s_cnt[j] == cstar);
    const int fl = (ci > cstar) || (ci == cstar && eqb < take);
    s_flag[i] = fl;
    __syncthreads();
    int slot = 0, start = 0;
    for (int j = 0; j < i; j++) {
        int f = s_flag[j];
        slot += f;
        start += f ? s_cnt[j] : 0;
    }
    s_slotof[i] = fl ? slot : -1;
    if (fl) { s_startsh[slot] = start; s_cntsh[slot] = ci; }
    __syncthreads();
    {
        const int r = s_par[i];
        const int sl = s_slotof[r];
        if (sl >= 0) {
            int pos = 0;
            for (int j = 0; j < i; j++) pos += (s_slotof[s_par[j]] == sl);
            int dst = s_startsh[sl] + pos;
            g_mem[b * NPIX + dst] = i;
            s_mem[dst] = i;
        }
    }
    __syncthreads();
    if (fl) {
        float sum = 0.f;
        for (int m = 0; m < ci; m++) sum += s_p[s_mem[start + m]];
        ss[slot] = (ci > 0) ? (sum / (float)ci) : -INFINITY;
    }
    __syncthreads();
    if (i < KS) {
        const float sv = ss[i];
        int rank = 0;
        for (int k = 0; k < KS; k++) {
            float o = ss[k];
            rank += (o > sv) || (o == sv && k < i);
        }
        sfl[i] = (rank < MT);
    }
    __syncthreads();
    if (i < KS && sfl[i]) {
        int pos = 0;
        for (int k = 0; k < i; k++) pos += sfl[k];
        g_selstart[b * MT + pos] = s_startsh[i];
        g_selcnt[b * MT + pos]   = s_cntsh[i];
    }
}

// ---------------- Kernel 5: centers for selected slots -> out directly -----
__global__ void k_out(const float* __restrict__ tok2d, float* __restrict__ out) {
    const int tt = blockIdx.x, b = blockIdx.y, t = threadIdx.x;
    const int start = g_selstart[b * MT + tt];
    const int cnt   = g_selcnt[b * MT + tt];
    const int* mem = g_mem + b * NPIX + start;
    const float4* base = (const float4*)tok2d;
    float4 a0 = {0.f,0.f,0.f,0.f}, a1 = a0, a2 = a0, a3 = a0;
    int m = 0;
    for (; m + 4 <= cnt; m += 4) {
        int i0 = mem[m + 0], i1 = mem[m + 1], i2 = mem[m + 2], i3 = mem[m + 3];
        float4 v0 = base[(size_t)(b * NT + 1 + i0) * 256 + t];
        float4 v1 = base[(size_t)(b * NT + 1 + i1) * 256 + t];
        float4 v2 = base[(size_t)(b * NT + 1 + i2) * 256 + t];
        float4 v3 = base[(size_t)(b * NT + 1 + i3) * 256 + t];
        a0.x += v0.x; a0.y += v0.y; a0.z += v0.z; a0.w += v0.w;
        a1.x += v1.x; a1.y += v1.y; a1.z += v1.z; a1.w += v1.w;
        a2.x += v2.x; a2.y += v2.y; a2.z += v2.z; a2.w += v2.w;
        a3.x += v3.x; a3.y += v3.y; a3.z += v3.z; a3.w += v3.w;
    }
    for (; m < cnt; m++) {
        float4 v0 = base[(size_t)(b * NT + 1 + mem[m]) * 256 + t];
        a0.x += v0.x; a0.y += v0.y; a0.z += v0.z; a0.w += v0.w;
    }
    float4 acc;
    acc.x = (a0.x + a1.x) + (a2.x + a3.x);
    acc.y = (a0.y + a1.y) + (a2.y + a3.y);
    acc.z = (a0.z + a1.z) + (a2.z + a3.z);
    acc.w = (a0.w + a1.w) + (a2.w + a3.w);
    const float dv = fmaxf((float)cnt, 1.f);
    float4 c;
    c.x = acc.x / dv; c.y = acc.y / dv; c.z = acc.z / dv; c.w = acc.w / dv;
    ((float4*)out)[((size_t)b * MT + tt) * 256 + t] = c;
}

// ---------------------------------------------------------------------------
extern "C" void kernel_launch(void* const* d_in, const int* in_sizes, int n_in,
                              void* d_out, int out_size) {
    (void)in_sizes; (void)n_in; (void)out_size;
    const float* tok2d = (const float*)d_in[0];
    const float* dw_w  = (const float*)d_in[1];
    const float* pw_w  = (const float*)d_in[2];
    const float* pw_b  = (const float*)d_in[3];
    const float* q_w   = (const float*)d_in[4];
    const float* q_b   = (const float*)d_in[5];
    const float* v_w   = (const float*)d_in[6];
    float* out = (float*)d_out;

    k_qcls    <<<dim3(128, 8), 256>>>(tok2d, q_w);
    k_u       <<<dim3(8, 64, 2), 128>>>(v_w, q_b);
    k_sumu    <<<BB * DD / 4 / 256, 256>>>();
    k_affdw   <<<dim3(6, BB, 8), 384>>>(tok2d, dw_w, pw_w);
    k_cluster <<<BB, NPIX>>>(pw_b);
    k_out     <<<dim3(MT, BB), 256>>>(tok2d, out);
}

// round 17
// speedup vs baseline: 1.1225x; 1.1225x over previous
#include <cuda_runtime.h>
#include <cstdint>
#include <math.h>

#define HH 24
#define WW 24
#define NPIX 576
#define DD 1024
#define BB 32
#define KS 256
#define MT 128
#define NT 577

// ---------------- scratch (device globals; no allocation allowed) ----------
__device__ float g_affp[4][BB * NPIX * 9];   // partial 9-logits per d-quarter
__device__ float g_dotp[4][BB * NPIX];       // partial x.u per d-quarter
__device__ int   g_mem[BB * NPIX];           // member lists (grouped by slot)
__device__ float g_qpartT[8][BB * DD];       // partial Q_cls, layout [d*32+b]
__device__ float g_upart[64][BB * DD];       // partial u (per d-chunk)
__device__ float g_u[BB * DD];               // u = Q_cls @ v_w
__device__ int   g_selstart[BB * MT];        // member offsets of selected slots
__device__ int   g_selcnt[BB * MT];          // counts of selected slots

// ---------------- Kernel 1: Q_cls partials (transposed, shuffle-free) ------
__global__ void k_qcls(const float* __restrict__ tok2d,
                       const float* __restrict__ qw) {
    __shared__ float s_cls[128 * 33];
    __shared__ float s_qw[8 * 128];
    const int t = threadIdx.x, lane = t & 31, w = t >> 5;
    const int ec = blockIdx.y;
    const int d = blockIdx.x * 8 + w;
    for (int l = t; l < 32 * 128; l += 256) {
        int b = l >> 7, e = l & 127;
        s_cls[e * 33 + b] = tok2d[(size_t)b * NT * DD + ec * 128 + e];
    }
    for (int l = t; l < 8 * 128; l += 256) {
        int wd = l >> 7, e = l & 127;
        s_qw[l] = qw[(size_t)(blockIdx.x * 8 + wd) * DD + ec * 128 + e];
    }
    __syncthreads();
    float acc = 0.f;
    const float* qrow = &s_qw[w * 128];
#pragma unroll 8
    for (int e = 0; e < 128; e++)
        acc += qrow[e] * s_cls[e * 33 + lane];
    g_qpartT[ec][d * 32 + lane] = acc;
}

// ---------------- Kernel 2: u partials, 64 d-chunks x 2 b-halves -----------
__global__ void k_u(const float* __restrict__ vw,
                    const float* __restrict__ qb) {
    __shared__ float s_qc[16 * 16];
    const int t = threadIdx.x;
    const int e = blockIdx.x * 128 + t;
    const int dc0 = blockIdx.y * 16;
    const int b0 = blockIdx.z * 16;
    for (int l = t; l < 16 * 16; l += 128) {
        int d = l >> 4, b = l & 15;
        float v = qb[dc0 + d];
#pragma unroll
        for (int z = 0; z < 8; z++) v += g_qpartT[z][(dc0 + d) * 32 + b0 + b];
        s_qc[l] = v;
    }
    __syncthreads();
    float acc[16];
#pragma unroll
    for (int b = 0; b < 16; b++) acc[b] = 0.f;
#pragma unroll
    for (int dd = 0; dd < 16; dd++) {
        float v = vw[(size_t)(dc0 + dd) * DD + e];
        const float4* q4 = (const float4*)&s_qc[dd * 16];
#pragma unroll
        for (int jj = 0; jj < 4; jj++) {
            float4 q = q4[jj];
            acc[4 * jj + 0] += q.x * v;
            acc[4 * jj + 1] += q.y * v;
            acc[4 * jj + 2] += q.z * v;
            acc[4 * jj + 3] += q.w * v;
        }
    }
#pragma unroll
    for (int b = 0; b < 16; b++)
        g_upart[blockIdx.y][(b0 + b) * DD + e] = acc[b];
}

// ---------------- Kernel 2b: sum u partials (float4) -----------------------
__global__ void k_sumu() {
    int idx = blockIdx.x * 256 + threadIdx.x;
    float4 s = {0.f, 0.f, 0.f, 0.f};
#pragma unroll
    for (int z = 0; z < 64; z++) {
        float4 v = ((const float4*)g_upart[z])[idx];
        s.x += v.x; s.y += v.y; s.z += v.z; s.w += v.w;
    }
    ((float4*)g_u)[idx] = s;
}

// ---------------- Kernel 3: FUSED dwconv + pointwise + x.u dot -------------
// (round-15 config: 16 phases of 16-d-lane tiles, 4 d-quarters, frozen)
#define TL_ROW 28
#define TL_LANE 172
__global__ void __launch_bounds__(384) k_affdw(const float* __restrict__ tok2d,
                        const float* __restrict__ dww,
                        const float* __restrict__ pww) {
    __shared__ float s_tile[2][16 * TL_LANE];
    __shared__ float s_dw12[256 * 12];
    __shared__ float s_u[256];
    const int t  = threadIdx.x;
    const int h0 = blockIdx.x * 4;
    const int b  = blockIdx.y;
    const int z  = blockIdx.z;

    for (int l = t; l < 256 * 9; l += 384) {
        int dq = l / 9, k = l - dq * 9;
        s_dw12[dq * 12 + k] = dww[z * 256 * 9 + l];
    }
    if (t < 256) s_u[t] = g_u[b * DD + z * 256 + t];

    const int dl = t & 15;
    const int p0 = t >> 4;
    const int qr = p0 / 6;
    const int qw = (p0 % 6) * 4;

    const unsigned int s_tile_a =
        (unsigned int)__cvta_generic_to_shared(&s_tile[0][0]);
    const char* gsrc0 = (const char*)(tok2d + (size_t)(b * NT + 1) * DD + z * 256 + dl);
    const unsigned int lane_off = (unsigned int)((dl * TL_LANE) << 2);
    const float* pwbase = pww + z * 256 + dl;

    unsigned int spos[7];
    unsigned int goff[7];
    int          gsz[7];
    int niter = 0;
    {
        int r = 0, c = p0;
#pragma unroll
        for (int i = 0; i < 7; i++) {
            int l = t + i * 384;
            if (l < 2496) {
                int gh = h0 + r - 1;
                int gw = c - 1;
                bool ok = ((unsigned)gh < HH) && ((unsigned)gw < WW);
                spos[i] = (unsigned int)((r * TL_ROW + c) << 2);
                goff[i] = ok ? (unsigned int)(((gh * WW + gw) * DD) * 4) : 0u;
                gsz[i]  = ok ? 4 : 0;
                niter = i + 1;
                c += 24;
                if (c >= 26) { c -= 26; r += 1; }
            }
        }
    }

#define ISSUE(CH, BUF)                                                          \
    {                                                                           \
        const char* gsrc = gsrc0 + (CH) * 64;                                   \
        unsigned int sb = s_tile_a + ((BUF) ? (unsigned int)((16 * TL_LANE) << 2) : 0u) + lane_off; \
        _Pragma("unroll")                                                       \
        for (int i = 0; i < 7; i++) {                                           \
            if (i < niter) {                                                    \
                asm volatile("cp.async.ca.shared.global [%0], [%1], 4, %2;"     \
                             :: "r"(sb + spos[i]), "l"(gsrc + goff[i]), "r"(gsz[i])); \
            }                                                                   \
        }                                                                       \
        asm volatile("cp.async.commit_group;" ::: "memory");                    \
    }

    float acc[40];
#pragma unroll
    for (int i = 0; i < 40; i++) acc[i] = 0.f;

    ISSUE(0, 0)
    asm volatile("cp.async.wait_group 0;" ::: "memory");
    __syncthreads();

    for (int ch = 0; ch < 16; ch++) {
        if (ch < 15) ISSUE(ch + 1, (ch + 1) & 1)
        const int dq = ch * 16 + dl;
        float wd[9], wp[9];
        {
            const float4* w4 = (const float4*)&s_dw12[dq * 12];
            float4 a = w4[0], bb4 = w4[1], c4 = w4[2];
            wd[0]=a.x; wd[1]=a.y; wd[2]=a.z; wd[3]=a.w;
            wd[4]=bb4.x; wd[5]=bb4.y; wd[6]=bb4.z; wd[7]=bb4.w;
            wd[8]=c4.x;
            const float* pwp = pwbase + ch * 16;
#pragma unroll
            for (int o = 0; o < 9; o++) wp[o] = pwp[o * DD];
        }
        const float uv = s_u[dq];
        const float* tp = &s_tile[ch & 1][dl * TL_LANE];
        float tv[3][6];
#pragma unroll
        for (int kh = 0; kh < 3; kh++) {
            const float* rp = tp + (qr + kh) * TL_ROW + qw;
            float4 v4 = *(const float4*)rp;
            float2 v2 = *(const float2*)(rp + 4);
            tv[kh][0] = v4.x; tv[kh][1] = v4.y; tv[kh][2] = v4.z;
            tv[kh][3] = v4.w; tv[kh][4] = v2.x; tv[kh][5] = v2.y;
        }
#pragma unroll
        for (int px = 0; px < 4; px++) {
            float dwv = 0.f;
#pragma unroll
            for (int kh = 0; kh < 3; kh++)
#pragma unroll
                for (int kw = 0; kw < 3; kw++)
                    dwv += tv[kh][px + kw] * wd[kh * 3 + kw];
#pragma unroll
            for (int o = 0; o < 9; o++) acc[px * 9 + o] += dwv * wp[o];
            acc[36 + px] += tv[1][px + 1] * uv;
        }
        if (ch < 15) {
            asm volatile("cp.async.wait_group 0;" ::: "memory");
            __syncthreads();
        }
    }
#undef ISSUE

#pragma unroll
    for (int i = 0; i < 40; i++)
#pragma unroll
        for (int off = 8; off; off >>= 1)
            acc[i] += __shfl_xor_sync(0xffffffffu, acc[i], off);

    if (dl == 0) {
#pragma unroll
        for (int px = 0; px < 4; px++) {
            int n = (h0 + qr) * WW + qw + px;
            float* dst = &g_affp[z][(b * NPIX + n) * 9];
#pragma unroll
            for (int o = 0; o < 9; o++) dst[o] = acc[px * 9 + o];
            g_dotp[z][b * NPIX + n] = acc[36 + px];
        }
    }
}

// ---------------- Kernel 4: parents + clusters + scores + top-128 ----------
// serial O(N) loops replaced by Hillis-Steele scans (deterministic).
__global__ void k_cluster(const float* __restrict__ pwb) {
    __shared__ int s_par[NPIX], s_cnt[NPIX], s_hist[NPIX + 1];
    __shared__ int s_slotof[NPIX], s_slotpar[NPIX];
    __shared__ int s_scan[NPIX];
    __shared__ int s_startsh[KS], s_cntsh[KS];
    __shared__ int s_mem[NPIX];
    __shared__ float s_p[NPIX];
    __shared__ float ss[KS];
    __shared__ int sfl[KS];
    __shared__ int s_cstar, s_take;
    const int i = threadIdx.x;
    const int b = blockIdx.x;

    {
        float pv = 0.f;
#pragma unroll
        for (int z = 0; z < 4; z++) pv += g_dotp[z][b * NPIX + i];
        s_p[i] = pv;
    }
    {
        float l9[9];
#pragma unroll
        for (int o = 0; o < 9; o++) l9[o] = pwb[o];
#pragma unroll
        for (int z = 0; z < 4; z++) {
            const float* src = &g_affp[z][(b * NPIX + i) * 9];
#pragma unroll
            for (int o = 0; o < 9; o++) l9[o] += src[o];
        }
        float mx = -1e30f;
#pragma unroll
        for (int o = 0; o < 9; o++) mx = fmaxf(mx, l9[o]);
        float e[9];
#pragma unroll
        for (int o = 0; o < 9; o++) e[o] = expf(l9[o] - mx);
        const int h = i / WW, w = i - (i / WW) * WW;
        float cs[9]; int cid[9]; int m = 0;
        for (int k = 0; k < 9; k++) {
            int dy = k / 3 - 1, dx = k % 3 - 1;
            int ny = min(max(h + dy, 0), HH - 1);
            int nx = min(max(w + dx, 0), WW - 1);
            int col = ny * WW + nx;
            int found = -1;
            for (int jj = 0; jj < m; jj++) if (cid[jj] == col) { found = jj; break; }
            if (found >= 0) cs[found] += e[k];
            else { cid[m] = col; cs[m] = e[k]; m++; }
        }
        int best = cid[0]; float bs = cs[0];
        for (int jj = 1; jj < m; jj++)
            if (cs[jj] > bs || (cs[jj] == bs && cid[jj] < best)) { bs = cs[jj]; best = cid[jj]; }
        s_par[i] = best;
    }
    __syncthreads();
    for (int it = 0; it < 6; it++) {
        int v = s_par[s_par[i]];
        __syncthreads();
        s_par[i] = v;
        __syncthreads();
    }
    s_cnt[i] = 0; s_hist[i] = 0;
    if (i == 0) s_hist[NPIX] = 0;
    __syncthreads();
    atomicAdd(&s_cnt[s_par[i]], 1);
    __syncthreads();
    atomicAdd(&s_hist[s_cnt[i]], 1);
    __syncthreads();
    // ---- suffix scan of hist (in place): s_hist[v] = sum_{vv>=v} hist[vv] --
    for (int off = 1; off <= NPIX; off <<= 1) {
        int v = s_hist[i];
        if (i + off <= NPIX) v += s_hist[i + off];
        __syncthreads();
        s_hist[i] = v;
        __syncthreads();
    }
    // threshold: sfx[v+1] < KS <= sfx[v]
    if (s_hist[i + 1] < KS && s_hist[i] >= KS) {
        s_cstar = i;
        s_take = KS - s_hist[i + 1];
    }
    __syncthreads();
    const int cstar = s_cstar, take = s_take;
    const int ci = s_cnt[i];
    // ---- eqb: exclusive prefix of (cnt==cstar) ----
    const int ind_eq = (ci == cstar) ? 1 : 0;
    s_scan[i] = ind_eq;
    __syncthreads();
    for (int off = 1; off < NPIX; off <<= 1) {
        int v = s_scan[i];
        if (i >= off) v += s_scan[i - off];
        __syncthreads();
        s_scan[i] = v;
        __syncthreads();
    }
    const int eqb = s_scan[i] - ind_eq;
    const int fl = (ci > cstar) || (ci == cstar && eqb < take);
    __syncthreads();
    // ---- packed scan: slot (low 16) + start (high 16) ----
    const int packed = fl ? (1 | (ci << 16)) : 0;
    s_scan[i] = packed;
    __syncthreads();
    for (int off = 1; off < NPIX; off <<= 1) {
        int v = s_scan[i];
        if (i >= off) v += s_scan[i - off];
        __syncthreads();
        s_scan[i] = v;
        __syncthreads();
    }
    const int ex = s_scan[i] - packed;
    const int slot = ex & 0xFFFF;
    const int start = ex >> 16;
    s_slotof[i] = fl ? slot : -1;
    if (fl) { s_startsh[slot] = start; s_cntsh[slot] = ci; }
    __syncthreads();
    // ---- member lists: pos = rank-by-index within slot ----
    s_slotpar[i] = s_slotof[s_par[i]];
    __syncthreads();
    {
        const int sl = s_slotpar[i];
        if (sl >= 0) {
            int pos = 0;
            for (int j = 0; j < i; j++) pos += (s_slotpar[j] == sl);
            int dst = s_startsh[sl] + pos;
            g_mem[b * NPIX + dst] = i;
            s_mem[dst] = i;
        }
    }
    __syncthreads();
    if (fl) {
        float sum = 0.f;
        for (int m = 0; m < ci; m++) sum += s_p[s_mem[start + m]];
        ss[slot] = (ci > 0) ? (sum / (float)ci) : -INFINITY;
    }
    __syncthreads();
    if (i < KS) {
        const float sv = ss[i];
        int rank = 0;
        for (int k = 0; k < KS; k++) {
            float o = ss[k];
            rank += (o > sv) || (o == sv && k < i);
        }
        sfl[i] = (rank < MT);
    }
    __syncthreads();
    if (i < KS && sfl[i]) {
        int pos = 0;
        for (int k = 0; k < i; k++) pos += sfl[k];
        g_selstart[b * MT + pos] = s_startsh[i];
        g_selcnt[b * MT + pos]   = s_cntsh[i];
    }
}

// ---------------- Kernel 5: centers for selected slots -> out directly -----
__global__ void k_out(const float* __restrict__ tok2d, float* __restrict__ out) {
    const int tt = blockIdx.x, b = blockIdx.y, t = threadIdx.x;
    const int start = g_selstart[b * MT + tt];
    const int cnt   = g_selcnt[b * MT + tt];
    const int* mem = g_mem + b * NPIX + start;
    const float4* base = (const float4*)tok2d;
    float4 a0 = {0.f,0.f,0.f,0.f}, a1 = a0, a2 = a0, a3 = a0;
    int m = 0;
    for (; m + 4 <= cnt; m += 4) {
        int i0 = mem[m + 0], i1 = mem[m + 1], i2 = mem[m + 2], i3 = mem[m + 3];
        float4 v0 = base[(size_t)(b * NT + 1 + i0) * 256 + t];
        float4 v1 = base[(size_t)(b * NT + 1 + i1) * 256 + t];
        float4 v2 = base[(size_t)(b * NT + 1 + i2) * 256 + t];
        float4 v3 = base[(size_t)(b * NT + 1 + i3) * 256 + t];
        a0.x += v0.x; a0.y += v0.y; a0.z += v0.z; a0.w += v0.w;
        a1.x += v1.x; a1.y += v1.y; a1.z += v1.z; a1.w += v1.w;
        a2.x += v2.x; a2.y += v2.y; a2.z += v2.z; a2.w += v2.w;
        a3.x += v3.x; a3.y += v3.y; a3.z += v3.z; a3.w += v3.w;
    }
    for (; m < cnt; m++) {
        float4 v0 = base[(size_t)(b * NT + 1 + mem[m]) * 256 + t];
        a0.x += v0.x; a0.y += v0.y; a0.z += v0.z; a0.w += v0.w;
    }
    float4 acc;
    acc.x = (a0.x + a1.x) + (a2.x + a3.x);
    acc.y = (a0.y + a1.y) + (a2.y + a3.y);
    acc.z = (a0.z + a1.z) + (a2.z + a3.z);
    acc.w = (a0.w + a1.w) + (a2.w + a3.w);
    const float dv = fmaxf((float)cnt, 1.f);
    float4 c;
    c.x = acc.x / dv; c.y = acc.y / dv; c.z = acc.z / dv; c.w = acc.w / dv;
    ((float4*)out)[((size_t)b * MT + tt) * 256 + t] = c;
}

// ---------------------------------------------------------------------------
extern "C" void kernel_launch(void* const* d_in, const int* in_sizes, int n_in,
                              void* d_out, int out_size) {
    (void)in_sizes; (void)n_in; (void)out_size;
    const float* tok2d = (const float*)d_in[0];
    const float* dw_w  = (const float*)d_in[1];
    const float* pw_w  = (const float*)d_in[2];
    const float* pw_b  = (const float*)d_in[3];
    const float* q_w   = (const float*)d_in[4];
    const float* q_b   = (const float*)d_in[5];
    const float* v_w   = (const float*)d_in[6];
    float* out = (float*)d_out;

    k_qcls    <<<dim3(128, 8), 256>>>(tok2d, q_w);
    k_u       <<<dim3(8, 64, 2), 128>>>(v_w, q_b);
    k_sumu    <<<BB * DD / 4 / 256, 256>>>();
    k_affdw   <<<dim3(6, BB, 4), 384>>>(tok2d, dw_w, pw_w);
    k_cluster <<<BB, NPIX>>>(pw_b);
    k_out     <<<dim3(MT, BB), 256>>>(tok2d, out);
}